// round 3
// baseline (speedup 1.0000x reference)
#include <cuda_runtime.h>
#include <cuda_bf16.h>
#include <cuda_fp16.h>

// Problem constants (fixed by the reference)
#define BB 256
#define TT 1024
#define EE 32
#define HH 128
#define GG 512   // 4*H

// W_hh k-split: k in [0,REG_K) lives in registers, [REG_K,128) in smem
#define REG_K 56
#define REG_K4 (REG_K/4)            // 14 quads
#define SMEM_K4 ((HH-REG_K)/4)      // 18 quads

// Shared memory layout (bytes)
#define OFF_WIH   0
#define SZ_WIH    (8 * GG * 16)                 // [k4=8][j=512] float4 = 65536
#define OFF_WHH   (OFF_WIH + SZ_WIH)
#define SZ_WHH    (SMEM_K4 * GG * 16)           // 18*512*16 = 147456
#define OFF_BIAS  (OFF_WHH + SZ_WHH)
#define SZ_BIAS   (GG * 4)                      // 2048
#define OFF_H     (OFF_BIAS + SZ_BIAS)
#define SZ_H      (2 * HH * 4)                  // 1024
#define OFF_C     (OFF_H + SZ_H)
#define SZ_C      (2 * HH * 4)                  // 1024
#define OFF_GATES (OFF_C + SZ_C)
#define SZ_GATES  (2 * GG * 4)                  // 4096
#define OFF_XS    (OFF_GATES + SZ_GATES)
#define SZ_XS     (2 * 2 * 8 * 16)              // double-buffered [buf][row][k4] float4 = 512
#define SMEM_TOTAL (OFF_XS + SZ_XS)             // 221696

__device__ __forceinline__ float sigmoidf_fast(float x) {
    return 1.0f / (1.0f + __expf(-x));
}
__device__ __forceinline__ float tanhf_fast(float x) {
    return 2.0f / (1.0f + __expf(-2.0f * x)) - 1.0f;
}

// ---------------------------------------------------------------------------
// Kernel 1: embedded[b,t,:] = is_action ? action_emb[action_ids] : 0
// one thread per (slot, float4-of-E)
// ---------------------------------------------------------------------------
__global__ void embed_init_kernel(const int* __restrict__ action_ids,
                                  const int* __restrict__ is_action,
                                  const float* __restrict__ action_emb,
                                  float* __restrict__ emb) {
    int gid = blockIdx.x * blockDim.x + threadIdx.x;   // BB*TT*8 threads
    int slot = gid >> 3;
    int e4 = gid & 7;
    float4 v = make_float4(0.f, 0.f, 0.f, 0.f);
    if (is_action[slot]) {
        int aid = action_ids[slot];
        v = reinterpret_cast<const float4*>(action_emb + (size_t)aid * EE)[e4];
    }
    reinterpret_cast<float4*>(emb)[gid] = v;
}

// ---------------------------------------------------------------------------
// Kernel 2: ragged embedding-bag scatter: emb[slot] += obs_emb[id] where !is_action
// one (obs, float4) per thread; sorted slots -> contention ~4, REDG-friendly
// ---------------------------------------------------------------------------
__global__ void obs_scatter_kernel(const int* __restrict__ obs_ids,
                                   const int* __restrict__ obs_slot,
                                   const int* __restrict__ is_action,
                                   const float* __restrict__ obs_emb,
                                   float* __restrict__ emb,
                                   int n_threads) {
    int gid = blockIdx.x * blockDim.x + threadIdx.x;
    if (gid >= n_threads) return;
    int i = gid >> 3;
    int e4 = gid & 7;
    int slot = obs_slot[i];
    if (!is_action[slot]) {
        int id = obs_ids[i];
        float4 v = reinterpret_cast<const float4*>(obs_emb + (size_t)id * EE)[e4];
        float* dst = emb + (size_t)slot * EE + e4 * 4;
        atomicAdd(dst + 0, v.x);
        atomicAdd(dst + 1, v.y);
        atomicAdd(dst + 2, v.z);
        atomicAdd(dst + 3, v.w);
    }
}

// ---------------------------------------------------------------------------
// Kernel 3: persistent LSTM. One CTA per 2 batch rows, 512 threads
// (thread j owns gate column j). Weights resident: W_ih + W_hh[:,56:128] in
// smem (transposed [k4][j] float4), W_hh[:,0:56] in per-thread registers.
// Full fp32 math. Two __syncthreads per step, x prefetch double-buffered.
// ---------------------------------------------------------------------------
__global__ void __launch_bounds__(512, 1)
lstm_kernel(const float* __restrict__ W_ih, const float* __restrict__ W_hh,
            const float* __restrict__ b_ih, const float* __restrict__ b_hh,
            const int* __restrict__ lengths,
            const float* __restrict__ emb,      // [B,T,E]
            float* __restrict__ outs,           // [B,T,H]
            float* __restrict__ h_out,          // [B,H]
            float* __restrict__ c_out) {        // [B,H]
    extern __shared__ char smem[];
    float4* Wih_s  = reinterpret_cast<float4*>(smem + OFF_WIH);   // [8][512]
    float4* Whh_s  = reinterpret_cast<float4*>(smem + OFF_WHH);   // [18][512]
    float*  bias_s = reinterpret_cast<float*>(smem + OFF_BIAS);   // [512]
    float*  h_s    = reinterpret_cast<float*>(smem + OFF_H);      // [2][128]
    float*  c_s    = reinterpret_cast<float*>(smem + OFF_C);      // [2][128]
    float*  gates_s= reinterpret_cast<float*>(smem + OFF_GATES);  // [2][512]
    float4* xs4    = reinterpret_cast<float4*>(smem + OFF_XS);    // [2][2][8]

    const int tid = threadIdx.x;
    const int j = tid;                 // gate column 0..511
    const int b0 = blockIdx.x * 2;     // two batch rows per CTA

    // ---- one-time weight staging ----
    // W_ih [512][32] row-major -> smem transposed [k4][j]
    #pragma unroll
    for (int k4 = 0; k4 < 8; k4++)
        Wih_s[k4 * GG + j] = reinterpret_cast<const float4*>(W_ih + (size_t)j * EE)[k4];

    // W_hh [512][128]: k<REG_K -> registers, rest -> smem transposed
    float w_reg[REG_K];
    #pragma unroll
    for (int k = 0; k < REG_K; k++)
        w_reg[k] = W_hh[(size_t)j * HH + k];
    #pragma unroll
    for (int k4 = 0; k4 < SMEM_K4; k4++)
        Whh_s[k4 * GG + j] =
            reinterpret_cast<const float4*>(W_hh + (size_t)j * HH + REG_K)[k4];

    bias_s[j] = b_ih[j] + b_hh[j];
    if (tid < 2 * HH) { h_s[tid] = 0.f; c_s[tid] = 0.f; }

    const int len0 = lengths[b0];
    const int len1 = lengths[b0 + 1];

    // x prefetch: 16 loader threads, each one float4 of x for (row, k4)
    const bool loader = (tid < 16);
    const int lr = tid >> 3, lk = tid & 7;
    float4 xreg = make_float4(0.f, 0.f, 0.f, 0.f);
    if (loader)
        xreg = reinterpret_cast<const float4*>(
                   emb + ((size_t)(b0 + lr) * TT + 0) * EE)[lk];

    const float4* h4 = reinterpret_cast<const float4*>(h_s);  // [2][32]

    for (int t = 0; t < TT; t++) {
        if (loader) xs4[(t & 1) * 16 + lr * 8 + lk] = xreg;
        __syncthreads();   // x(t) staged, h(t-1) final

        // ---- gate GEMM: acc[r] = bias + x.Wih^T + h.Whh^T for column j ----
        float acc0 = bias_s[j];
        float acc1 = acc0;

        const float4* xb = xs4 + (t & 1) * 16;
        #pragma unroll
        for (int k4 = 0; k4 < 8; k4++) {
            float4 w  = Wih_s[k4 * GG + j];
            float4 x0 = xb[k4];
            float4 x1 = xb[8 + k4];
            acc0 = fmaf(w.x, x0.x, acc0); acc0 = fmaf(w.y, x0.y, acc0);
            acc0 = fmaf(w.z, x0.z, acc0); acc0 = fmaf(w.w, x0.w, acc0);
            acc1 = fmaf(w.x, x1.x, acc1); acc1 = fmaf(w.y, x1.y, acc1);
            acc1 = fmaf(w.z, x1.z, acc1); acc1 = fmaf(w.w, x1.w, acc1);
        }
        // register-resident weight part: k in [0, REG_K)
        #pragma unroll
        for (int k4 = 0; k4 < REG_K4; k4++) {
            float4 h0 = h4[k4];
            float4 h1 = h4[32 + k4];
            float w0 = w_reg[k4 * 4 + 0], w1 = w_reg[k4 * 4 + 1];
            float w2 = w_reg[k4 * 4 + 2], w3 = w_reg[k4 * 4 + 3];
            acc0 = fmaf(w0, h0.x, acc0); acc0 = fmaf(w1, h0.y, acc0);
            acc0 = fmaf(w2, h0.z, acc0); acc0 = fmaf(w3, h0.w, acc0);
            acc1 = fmaf(w0, h1.x, acc1); acc1 = fmaf(w1, h1.y, acc1);
            acc1 = fmaf(w2, h1.z, acc1); acc1 = fmaf(w3, h1.w, acc1);
        }
        // smem weight part: k in [REG_K, 128)
        #pragma unroll
        for (int k4 = 0; k4 < SMEM_K4; k4++) {
            float4 w  = Whh_s[k4 * GG + j];
            float4 h0 = h4[REG_K4 + k4];
            float4 h1 = h4[32 + REG_K4 + k4];
            acc0 = fmaf(w.x, h0.x, acc0); acc0 = fmaf(w.y, h0.y, acc0);
            acc0 = fmaf(w.z, h0.z, acc0); acc0 = fmaf(w.w, h0.w, acc0);
            acc1 = fmaf(w.x, h1.x, acc1); acc1 = fmaf(w.y, h1.y, acc1);
            acc1 = fmaf(w.z, h1.z, acc1); acc1 = fmaf(w.w, h1.w, acc1);
        }
        gates_s[j] = acc0;
        gates_s[GG + j] = acc1;

        // prefetch x(t+1) — latency hidden behind sync + pointwise
        if (loader && (t + 1) < TT)
            xreg = reinterpret_cast<const float4*>(
                       emb + ((size_t)(b0 + lr) * TT + (t + 1)) * EE)[lk];

        __syncthreads();   // gates ready

        // ---- pointwise LSTM cell (256 threads: (row, hcol)) ----
        if (tid < 2 * HH) {
            int r = tid >> 7;
            int hc = tid & (HH - 1);
            const float* g = gates_s + r * GG;
            float gi = g[hc];
            float gf = g[HH + hc];
            float gg = g[2 * HH + hc];
            float go = g[3 * HH + hc];
            float i_ = sigmoidf_fast(gi);
            float f_ = sigmoidf_fast(gf);
            float g_ = tanhf_fast(gg);
            float o_ = sigmoidf_fast(go);
            float cold = c_s[tid];
            float cn = fmaf(f_, cold, i_ * g_);
            float hn = o_ * tanhf_fast(cn);
            int len = r ? len1 : len0;
            bool m = (t < len);
            float hold = h_s[tid];
            h_s[tid] = m ? hn : hold;
            c_s[tid] = m ? cn : cold;
            outs[((size_t)(b0 + r) * TT + t) * HH + hc] = m ? hn : 0.f;
        }
        // no third sync needed: next iteration's __syncthreads() (after the
        // xs store, which touches the other buffer) orders h/c updates
        // before the next GEMM reads them.
    }

    if (tid < 2 * HH) {
        int r = tid >> 7;
        int hc = tid & (HH - 1);
        h_out[(size_t)(b0 + r) * HH + hc] = h_s[tid];
        c_out[(size_t)(b0 + r) * HH + hc] = c_s[tid];
    }
}

// ---------------------------------------------------------------------------
// kernel_launch — graph-capturable: 3 launches on the default stream.
// Output layout (reference tuple order): outputs[B,T,H] | h[1,B,H] | c[1,B,H] | embedded[B,T,E]
// ---------------------------------------------------------------------------
extern "C" void kernel_launch(void* const* d_in, const int* in_sizes, int n_in,
                              void* d_out, int out_size) {
    const int*   obs_ids     = (const int*)d_in[0];
    const int*   obs_slot    = (const int*)d_in[1];
    const int*   action_ids  = (const int*)d_in[2];
    const int*   is_action   = (const int*)d_in[3];
    const int*   lengths     = (const int*)d_in[4];
    const float* action_emb  = (const float*)d_in[5];
    const float* obs_emb     = (const float*)d_in[6];
    const float* W_ih        = (const float*)d_in[7];
    const float* W_hh        = (const float*)d_in[8];
    const float* b_ih        = (const float*)d_in[9];
    const float* b_hh        = (const float*)d_in[10];

    float* out   = (float*)d_out;
    float* outs  = out;                                    // B*T*H
    float* h_out = out + (size_t)BB * TT * HH;             // B*H
    float* c_out = h_out + (size_t)BB * HH;                // B*H
    float* emb   = c_out + (size_t)BB * HH;                // B*T*E

    // opt-in to >48KB dynamic smem (capture-safe, idempotent)
    cudaFuncSetAttribute(lstm_kernel,
                         cudaFuncAttributeMaxDynamicSharedMemorySize, SMEM_TOTAL);

    // 1) embedded = is_action ? action_emb[aid] : 0
    {
        int nthreads = BB * TT * 8;
        embed_init_kernel<<<nthreads / 256, 256>>>(action_ids, is_action,
                                                   action_emb, emb);
    }
    // 2) scatter-add observation embeddings into non-action slots
    {
        int n_obs = in_sizes[0];
        int nthreads = n_obs * 8;
        int blocks = (nthreads + 255) / 256;
        obs_scatter_kernel<<<blocks, 256>>>(obs_ids, obs_slot, is_action,
                                            obs_emb, emb, nthreads);
    }
    // 3) persistent LSTM: 128 CTAs x 512 threads, 1 CTA/SM
    lstm_kernel<<<BB / 2, 512, SMEM_TOTAL>>>(W_ih, W_hh, b_ih, b_hh, lengths,
                                             emb, outs, h_out, c_out);
}

// round 4
// speedup vs baseline: 1.1443x; 1.1443x over previous
#include <cuda_runtime.h>
#include <cuda_bf16.h>
#include <cuda_fp16.h>

// Problem constants (fixed by the reference)
#define BB 256
#define TT 1024
#define EE 32
#define HH 128
#define GG 512   // 4*H
#define SLOTS (BB * TT)

typedef unsigned long long u64;

// ---- f32x2 packed FMA (Blackwell FFMA2: only reachable via PTX) ----
__device__ __forceinline__ u64 ffma2(u64 a, u64 b, u64 c) {
    u64 d;
    asm("fma.rn.f32x2 %0, %1, %2, %3;" : "=l"(d) : "l"(a), "l"(b), "l"(c));
    return d;
}
__device__ __forceinline__ u64 packf2(float lo, float hi) {
    u64 d;
    asm("mov.b64 %0, {%1, %2};" : "=l"(d) : "f"(lo), "f"(hi));
    return d;
}
__device__ __forceinline__ float2 unpackf2(u64 v) {
    float2 r;
    asm("mov.b64 {%0, %1}, %2;" : "=f"(r.x), "=f"(r.y) : "l"(v));
    return r;
}

__device__ __forceinline__ float sigmoidf_fast(float x) {
    return 1.0f / (1.0f + __expf(-x));
}
__device__ __forceinline__ float tanhf_fast(float x) {
    return 2.0f / (1.0f + __expf(-2.0f * x)) - 1.0f;
}

// 512 MB scratch: precomputed x-projection gate_x[slot][512] = bias + x.Wih^T
__device__ float g_gx[(size_t)SLOTS * GG];

// ---------------------------------------------------------------------------
// Kernel 1: embedded[b,t,:] = is_action ? action_emb[action_ids] : 0
// ---------------------------------------------------------------------------
__global__ void embed_init_kernel(const int* __restrict__ action_ids,
                                  const int* __restrict__ is_action,
                                  const float* __restrict__ action_emb,
                                  float* __restrict__ emb) {
    int gid = blockIdx.x * blockDim.x + threadIdx.x;   // BB*TT*8 threads
    int slot = gid >> 3;
    int e4 = gid & 7;
    float4 v = make_float4(0.f, 0.f, 0.f, 0.f);
    if (is_action[slot]) {
        int aid = action_ids[slot];
        v = reinterpret_cast<const float4*>(action_emb + (size_t)aid * EE)[e4];
    }
    reinterpret_cast<float4*>(emb)[gid] = v;
}

// ---------------------------------------------------------------------------
// Kernel 2: ragged embedding-bag scatter: emb[slot] += obs_emb[id] if !is_action
// ---------------------------------------------------------------------------
__global__ void obs_scatter_kernel(const int* __restrict__ obs_ids,
                                   const int* __restrict__ obs_slot,
                                   const int* __restrict__ is_action,
                                   const float* __restrict__ obs_emb,
                                   float* __restrict__ emb,
                                   int n_threads) {
    int gid = blockIdx.x * blockDim.x + threadIdx.x;
    if (gid >= n_threads) return;
    int i = gid >> 3;
    int e4 = gid & 7;
    int slot = obs_slot[i];
    if (!is_action[slot]) {
        int id = obs_ids[i];
        float4 v = reinterpret_cast<const float4*>(obs_emb + (size_t)id * EE)[e4];
        float* dst = emb + (size_t)slot * EE + e4 * 4;
        atomicAdd(dst + 0, v.x);
        atomicAdd(dst + 1, v.y);
        atomicAdd(dst + 2, v.z);
        atomicAdd(dst + 3, v.w);
    }
}

// ---------------------------------------------------------------------------
// Kernel 3: gate_x pre-GEMM. gx[slot][j] = (b_ih+b_hh)[j] + emb[slot,:].Wih[j,:]
// 256 threads, each owns cols j and j+256 with Wih rows in registers (FFMA2).
// Chunks of 64 slots staged in smem, fully parallel over 262144 slots.
// ---------------------------------------------------------------------------
#define XCHUNK 64
__global__ void __launch_bounds__(256, 2)
gatex_kernel(const float* __restrict__ emb, const float* __restrict__ W_ih,
             const float* __restrict__ b_ih, const float* __restrict__ b_hh) {
    __shared__ float xs[XCHUNK * EE];    // 8 KB
    const int tid = threadIdx.x;
    const int j0 = tid;
    const int j1 = tid + 256;

    // Wih rows for the two owned columns, packed along k as f32x2 (16 u64 each)
    u64 w0[16], w1[16];
    {
        const ulonglong2* s0 = reinterpret_cast<const ulonglong2*>(W_ih + (size_t)j0 * EE);
        const ulonglong2* s1 = reinterpret_cast<const ulonglong2*>(W_ih + (size_t)j1 * EE);
        #pragma unroll
        for (int i = 0; i < 8; i++) {
            ulonglong2 a = s0[i]; w0[2*i] = a.x; w0[2*i+1] = a.y;
            ulonglong2 b = s1[i]; w1[2*i] = b.x; w1[2*i+1] = b.y;
        }
    }
    const float bias0 = b_ih[j0] + b_hh[j0];
    const float bias1 = b_ih[j1] + b_hh[j1];

    const int base = blockIdx.x * XCHUNK;   // grid covers all chunks exactly

    // cooperative stage: 64 slots x 32 floats = 512 float4, 2 per thread
    {
        const float4* src = reinterpret_cast<const float4*>(emb + (size_t)base * EE);
        reinterpret_cast<float4*>(xs)[tid] = src[tid];
        reinterpret_cast<float4*>(xs)[tid + 256] = src[tid + 256];
    }
    __syncthreads();

    #pragma unroll 2
    for (int s = 0; s < XCHUNK; s++) {
        const ulonglong2* xv = reinterpret_cast<const ulonglong2*>(xs + s * EE);
        u64 a0 = packf2(bias0, 0.f);
        u64 a1 = packf2(bias1, 0.f);
        #pragma unroll
        for (int k4 = 0; k4 < 8; k4++) {
            ulonglong2 x = xv[k4];
            a0 = ffma2(w0[2*k4],     x.x, a0);
            a0 = ffma2(w0[2*k4 + 1], x.y, a0);
            a1 = ffma2(w1[2*k4],     x.x, a1);
            a1 = ffma2(w1[2*k4 + 1], x.y, a1);
        }
        float2 r0 = unpackf2(a0);
        float2 r1 = unpackf2(a1);
        size_t o = (size_t)(base + s) * GG;
        g_gx[o + j0] = r0.x + r0.y;
        g_gx[o + j1] = r1.x + r1.y;
    }
}

// ---------------------------------------------------------------------------
// Kernel 4: persistent LSTM recurrence. One CTA per 2 batch rows, 512 threads
// (thread j owns gate column j, both rows). W_hh[:,0:56] in registers (packed
// f32x2), W_hh[:,56:128] in smem transposed [k4][j]. x-projection read from
// g_gx with a 1-step register prefetch. All math exact fp32 via FFMA2.
// ---------------------------------------------------------------------------
#define REG_K 56
#define REG_K4 (REG_K / 4)            // 14
#define SMEM_K4 ((HH - REG_K) / 4)    // 18

#define OFF_WHH   0
#define SZ_WHH    (SMEM_K4 * GG * 16)     // 147456
#define OFF_H     (OFF_WHH + SZ_WHH)
#define SZ_H      (2 * HH * 4)            // 1024
#define OFF_C     (OFF_H + SZ_H)
#define SZ_C      (2 * HH * 4)
#define OFF_GATES (OFF_C + SZ_C)
#define SZ_GATES  (2 * GG * 4)            // 4096
#define SMEM_TOTAL (OFF_GATES + SZ_GATES) // 153600

__global__ void __launch_bounds__(512, 1)
lstm_kernel(const float* __restrict__ W_hh,
            const int* __restrict__ lengths,
            float* __restrict__ outs,           // [B,T,H]
            float* __restrict__ h_out,          // [B,H]
            float* __restrict__ c_out) {        // [B,H]
    extern __shared__ char smem[];
    ulonglong2* Whh_s  = reinterpret_cast<ulonglong2*>(smem + OFF_WHH);  // [18][512]
    float*      h_s    = reinterpret_cast<float*>(smem + OFF_H);         // [2][128]
    float*      c_s    = reinterpret_cast<float*>(smem + OFF_C);
    float*      gates_s= reinterpret_cast<float*>(smem + OFF_GATES);     // [2][512]

    const int tid = threadIdx.x;
    const int j = tid;
    const int b0 = blockIdx.x * 2;

    // ---- one-time weight staging ----
    u64 wr[REG_K / 2];   // 28 packed f32x2 = W_hh[j][0:56]
    {
        const ulonglong2* src = reinterpret_cast<const ulonglong2*>(W_hh + (size_t)j * HH);
        #pragma unroll
        for (int i = 0; i < REG_K4; i++) {
            ulonglong2 v = src[i];
            wr[2*i] = v.x; wr[2*i + 1] = v.y;
        }
        const ulonglong2* src2 = reinterpret_cast<const ulonglong2*>(W_hh + (size_t)j * HH + REG_K);
        #pragma unroll
        for (int k4 = 0; k4 < SMEM_K4; k4++)
            Whh_s[k4 * GG + j] = src2[k4];
    }
    if (tid < 2 * HH) { h_s[tid] = 0.f; c_s[tid] = 0.f; }

    const int len0 = lengths[b0];
    const int len1 = lengths[b0 + 1];

    const float* gx0p = g_gx + ((size_t)b0 * TT) * GG + j;        // row 0, t=0
    const float* gx1p = g_gx + ((size_t)(b0 + 1) * TT) * GG + j;  // row 1, t=0

    float gx0 = __ldg(gx0p);
    float gx1 = __ldg(gx1p);

    const ulonglong2* h2r = reinterpret_cast<const ulonglong2*>(h_s); // [2][32]

    for (int t = 0; t < TT; t++) {
        __syncthreads();   // h(t-1)/c(t-1) finalized; gates_s(t-1) consumed

        u64 acc0 = packf2(gx0, 0.f);
        u64 acc1 = packf2(gx1, 0.f);

        // prefetch gate_x(t+1) — latency hidden behind the GEMM below
        int tn = (t + 1 < TT) ? (t + 1) : t;
        gx0 = __ldg(gx0p + (size_t)tn * GG);
        gx1 = __ldg(gx1p + (size_t)tn * GG);

        // ---- h·Whh^T, register-weight part: k in [0, 56) ----
        #pragma unroll
        for (int k4 = 0; k4 < REG_K4; k4++) {
            ulonglong2 h0 = h2r[k4];
            ulonglong2 h1 = h2r[32 + k4];
            acc0 = ffma2(wr[2*k4],     h0.x, acc0);
            acc0 = ffma2(wr[2*k4 + 1], h0.y, acc0);
            acc1 = ffma2(wr[2*k4],     h1.x, acc1);
            acc1 = ffma2(wr[2*k4 + 1], h1.y, acc1);
        }
        // ---- smem-weight part: k in [56, 128) ----
        #pragma unroll
        for (int k4 = 0; k4 < SMEM_K4; k4++) {
            ulonglong2 w  = Whh_s[k4 * GG + j];
            ulonglong2 h0 = h2r[REG_K4 + k4];
            ulonglong2 h1 = h2r[32 + REG_K4 + k4];
            acc0 = ffma2(w.x, h0.x, acc0);
            acc0 = ffma2(w.y, h0.y, acc0);
            acc1 = ffma2(w.x, h1.x, acc1);
            acc1 = ffma2(w.y, h1.y, acc1);
        }
        float2 a0 = unpackf2(acc0);
        float2 a1 = unpackf2(acc1);
        gates_s[j]      = a0.x + a0.y;
        gates_s[GG + j] = a1.x + a1.y;

        __syncthreads();   // gates ready

        // ---- pointwise LSTM cell: 256 threads = (row, hcol) ----
        if (tid < 2 * HH) {
            int r = tid >> 7;
            int hc = tid & (HH - 1);
            const float* g = gates_s + r * GG;
            float gi = g[hc];
            float gf = g[HH + hc];
            float gg = g[2 * HH + hc];
            float go = g[3 * HH + hc];
            float i_ = sigmoidf_fast(gi);
            float f_ = sigmoidf_fast(gf);
            float g_ = tanhf_fast(gg);
            float o_ = sigmoidf_fast(go);
            float cold = c_s[tid];
            float cn = fmaf(f_, cold, i_ * g_);
            float hn = o_ * tanhf_fast(cn);
            int len = r ? len1 : len0;
            bool m = (t < len);
            float hold = h_s[tid];
            h_s[tid] = m ? hn : hold;
            c_s[tid] = m ? cn : cold;
            outs[((size_t)(b0 + r) * TT + t) * HH + hc] = m ? hn : 0.f;
        }
        // next iteration's loop-top __syncthreads orders h/c writes before reads
    }

    if (tid < 2 * HH) {
        int r = tid >> 7;
        int hc = tid & (HH - 1);
        h_out[(size_t)(b0 + r) * HH + hc] = h_s[tid];
        c_out[(size_t)(b0 + r) * HH + hc] = c_s[tid];
    }
}

// ---------------------------------------------------------------------------
// kernel_launch — graph-capturable: 4 launches on the default stream.
// Output: outputs[B,T,H] | h[1,B,H] | c[1,B,H] | embedded[B,T,E]
// ---------------------------------------------------------------------------
extern "C" void kernel_launch(void* const* d_in, const int* in_sizes, int n_in,
                              void* d_out, int out_size) {
    const int*   obs_ids     = (const int*)d_in[0];
    const int*   obs_slot    = (const int*)d_in[1];
    const int*   action_ids  = (const int*)d_in[2];
    const int*   is_action   = (const int*)d_in[3];
    const int*   lengths     = (const int*)d_in[4];
    const float* action_emb  = (const float*)d_in[5];
    const float* obs_emb     = (const float*)d_in[6];
    const float* W_ih        = (const float*)d_in[7];
    const float* W_hh        = (const float*)d_in[8];
    const float* b_ih        = (const float*)d_in[9];
    const float* b_hh        = (const float*)d_in[10];

    float* out   = (float*)d_out;
    float* outs  = out;                                    // B*T*H
    float* h_out = out + (size_t)BB * TT * HH;             // B*H
    float* c_out = h_out + (size_t)BB * HH;                // B*H
    float* emb   = c_out + (size_t)BB * HH;                // B*T*E

    cudaFuncSetAttribute(lstm_kernel,
                         cudaFuncAttributeMaxDynamicSharedMemorySize, SMEM_TOTAL);

    // 1) embedded = is_action ? action_emb[aid] : 0
    {
        int nthreads = BB * TT * 8;
        embed_init_kernel<<<nthreads / 256, 256>>>(action_ids, is_action,
                                                   action_emb, emb);
    }
    // 2) scatter-add observation embeddings into non-action slots
    {
        int n_obs = in_sizes[0];
        int nthreads = n_obs * 8;
        int blocks = (nthreads + 255) / 256;
        obs_scatter_kernel<<<blocks, 256>>>(obs_ids, obs_slot, is_action,
                                            obs_emb, emb, nthreads);
    }
    // 3) x-projection pre-GEMM: gx = bias + emb @ Wih^T  (262144 x 512)
    gatex_kernel<<<SLOTS / XCHUNK, 256>>>(emb, W_ih, b_ih, b_hh);

    // 4) persistent LSTM recurrence: 128 CTAs x 512 threads, 1 CTA/SM
    lstm_kernel<<<BB / 2, 512, SMEM_TOTAL>>>(W_hh, lengths, outs, h_out, c_out);
}

// round 7
// speedup vs baseline: 1.4897x; 1.3018x over previous
#include <cuda_runtime.h>
#include <cuda_bf16.h>
#include <cuda_fp16.h>

// Problem constants (fixed by the reference)
#define BB 256
#define TT 1024
#define EE 32
#define HH 128
#define GG 512   // 4*H
#define SLOTS (BB * TT)

typedef unsigned long long u64;

// ---- f32x2 packed FMA (Blackwell FFMA2: only reachable via PTX) ----
__device__ __forceinline__ u64 ffma2(u64 a, u64 b, u64 c) {
    u64 d;
    asm("fma.rn.f32x2 %0, %1, %2, %3;" : "=l"(d) : "l"(a), "l"(b), "l"(c));
    return d;
}
__device__ __forceinline__ float2 unpackf2(u64 v) {
    float2 r;
    asm("mov.b64 {%0, %1}, %2;" : "=f"(r.x), "=f"(r.y) : "l"(v));
    return r;
}

__device__ __forceinline__ float sigmoidf_fast(float x) {
    return 1.0f / (1.0f + __expf(-x));
}
__device__ __forceinline__ float tanhf_fast(float x) {
    return 2.0f / (1.0f + __expf(-2.0f * x)) - 1.0f;
}

// 512 MB scratch: precomputed x-projection gate_x[slot][512] = bias + x.Wih^T
__device__ float g_gx[(size_t)SLOTS * GG];

// ---------------------------------------------------------------------------
// Kernel 1: embedded[b,t,:] = is_action ? action_emb[action_ids] : 0
// ---------------------------------------------------------------------------
__global__ void embed_init_kernel(const int* __restrict__ action_ids,
                                  const int* __restrict__ is_action,
                                  const float* __restrict__ action_emb,
                                  float* __restrict__ emb) {
    int gid = blockIdx.x * blockDim.x + threadIdx.x;   // BB*TT*8 threads
    int slot = gid >> 3;
    int e4 = gid & 7;
    float4 v = make_float4(0.f, 0.f, 0.f, 0.f);
    if (is_action[slot]) {
        int aid = action_ids[slot];
        v = reinterpret_cast<const float4*>(action_emb + (size_t)aid * EE)[e4];
    }
    reinterpret_cast<float4*>(emb)[gid] = v;
}

// ---------------------------------------------------------------------------
// Kernel 2: ragged embedding-bag scatter: emb[slot] += obs_emb[id] if !is_action
// ---------------------------------------------------------------------------
__global__ void obs_scatter_kernel(const int* __restrict__ obs_ids,
                                   const int* __restrict__ obs_slot,
                                   const int* __restrict__ is_action,
                                   const float* __restrict__ obs_emb,
                                   float* __restrict__ emb,
                                   int n_threads) {
    int gid = blockIdx.x * blockDim.x + threadIdx.x;
    if (gid >= n_threads) return;
    int i = gid >> 3;
    int e4 = gid & 7;
    int slot = obs_slot[i];
    if (!is_action[slot]) {
        int id = obs_ids[i];
        float4 v = reinterpret_cast<const float4*>(obs_emb + (size_t)id * EE)[e4];
        float* dst = emb + (size_t)slot * EE + e4 * 4;
        atomicAdd(dst + 0, v.x);
        atomicAdd(dst + 1, v.y);
        atomicAdd(dst + 2, v.z);
        atomicAdd(dst + 3, v.w);
    }
}

// ---------------------------------------------------------------------------
// Kernel 3: gate_x pre-GEMM. gx[slot][j] = (b_ih+b_hh)[j] + emb[slot,:].Wih[j,:]
// ---------------------------------------------------------------------------
#define XCHUNK 64
__global__ void __launch_bounds__(256, 2)
gatex_kernel(const float* __restrict__ emb, const float* __restrict__ W_ih,
             const float* __restrict__ b_ih, const float* __restrict__ b_hh) {
    __shared__ float xs[XCHUNK * EE];    // 8 KB
    const int tid = threadIdx.x;
    const int j0 = tid;
    const int j1 = tid + 256;

    u64 w0[16], w1[16];
    {
        const ulonglong2* s0 = reinterpret_cast<const ulonglong2*>(W_ih + (size_t)j0 * EE);
        const ulonglong2* s1 = reinterpret_cast<const ulonglong2*>(W_ih + (size_t)j1 * EE);
        #pragma unroll
        for (int i = 0; i < 8; i++) {
            ulonglong2 a = s0[i]; w0[2*i] = a.x; w0[2*i+1] = a.y;
            ulonglong2 b = s1[i]; w1[2*i] = b.x; w1[2*i+1] = b.y;
        }
    }
    const float bias0 = b_ih[j0] + b_hh[j0];
    const float bias1 = b_ih[j1] + b_hh[j1];

    const int base = blockIdx.x * XCHUNK;

    {
        const float4* src = reinterpret_cast<const float4*>(emb + (size_t)base * EE);
        reinterpret_cast<float4*>(xs)[tid] = src[tid];
        reinterpret_cast<float4*>(xs)[tid + 256] = src[tid + 256];
    }
    __syncthreads();

    #pragma unroll 2
    for (int s = 0; s < XCHUNK; s++) {
        const ulonglong2* xv = reinterpret_cast<const ulonglong2*>(xs + s * EE);
        u64 a0 = 0ull, a1 = 0ull;
        #pragma unroll
        for (int k4 = 0; k4 < 8; k4++) {
            ulonglong2 x = xv[k4];
            a0 = ffma2(w0[2*k4],     x.x, a0);
            a0 = ffma2(w0[2*k4 + 1], x.y, a0);
            a1 = ffma2(w1[2*k4],     x.x, a1);
            a1 = ffma2(w1[2*k4 + 1], x.y, a1);
        }
        float2 r0 = unpackf2(a0);
        float2 r1 = unpackf2(a1);
        size_t o = (size_t)(base + s) * GG;
        g_gx[o + j0] = bias0 + r0.x + r0.y;
        g_gx[o + j1] = bias1 + r1.x + r1.y;
    }
}

// ---------------------------------------------------------------------------
// Kernel 4: persistent LSTM recurrence, k-split + column-pair decomposition.
// 512 threads = 256 column-pairs x 2 k-halves. Thread (j2, q) computes partial
// gate dots for columns {j2, j2+256}, rows {0,1}, k in [64q, 64q+64).
//   - k_local 0..39 (40 floats/col) in registers (f32x2 packed)
//   - k_local 40..63 (24 floats/col) streamed from smem (12 LDS.128/step)
//   - h broadcast: only its own k-half (32 LDS.128/step)
// k-reduction via an 8KB partials buffer; thread (j2<128, q) finalizes
// (row=q, hc=j2): gathers partner partials, adds gx, runs activations with
// c resident in registers. Exact fp32 everywhere.
//
// wa layout (FIXED this round — was OOB at wa[40..59], UB since R4):
//   wa[0..19]  = col0 held weights (f32x2, k_local 0..39)
//   wa[20..39] = col1 held weights (f32x2, k_local 0..39)
// ---------------------------------------------------------------------------
#define HELD_PAIRS 20            // f32x2 regs per col (k_local 0..39)
#define STR_QUADS  6             // float4 per col streamed (k_local 40..63)

#define OFF_WS 0
#define SZ_WS  (2 * STR_QUADS * 512 * 16)    // 98304
#define OFF_H  (OFF_WS + SZ_WS)
#define SZ_H   (2 * HH * 4)                  // 1024
#define OFF_P  (OFF_H + SZ_H)
#define SZ_P   (512 * 16)                    // 8192
#define SMEM_TOTAL (OFF_P + SZ_P)            // 107520

__global__ void __launch_bounds__(512, 1)
lstm_kernel(const float* __restrict__ W_hh,
            const int* __restrict__ lengths,
            float* __restrict__ outs,           // [B,T,H]
            float* __restrict__ h_out,          // [B,H]
            float* __restrict__ c_out) {        // [B,H]
    extern __shared__ char smem[];
    float4* WS  = reinterpret_cast<float4*>(smem + OFF_WS);   // [2*6][512]
    float*  h_s = reinterpret_cast<float*>(smem + OFF_H);     // [2][128]
    float4* P   = reinterpret_cast<float4*>(smem + OFF_P);    // [512]

    const int tid = threadIdx.x;
    const int j2  = tid & 255;
    const int q   = tid >> 8;          // k-half
    const int b0  = blockIdx.x * 2;
    const int col0 = j2;
    const int col1 = j2 + 256;
    const int kbase = q * 64;

    // ---- one-time weight staging ----
    u64 wa[2 * HELD_PAIRS];            // wa[0..19]=col0, wa[20..39]=col1
    {
        const ulonglong2* s0 = reinterpret_cast<const ulonglong2*>(W_hh + (size_t)col0 * HH + kbase);
        const ulonglong2* s1 = reinterpret_cast<const ulonglong2*>(W_hh + (size_t)col1 * HH + kbase);
        #pragma unroll
        for (int i = 0; i < HELD_PAIRS / 2; i++) {       // 10 float4 per col = k_local 0..39
            ulonglong2 a = s0[i]; wa[2*i] = a.x; wa[2*i+1] = a.y;
            // FIX: col1 lives at wa[HELD_PAIRS + ...] (20..39), NOT 2*HELD_PAIRS (OOB)
            ulonglong2 b = s1[i]; wa[HELD_PAIRS + 2*i] = b.x; wa[HELD_PAIRS + 2*i+1] = b.y;
        }
        // streamed region: k_local 40..63 = +2*HELD_PAIRS floats
        const float4* t0 = reinterpret_cast<const float4*>(W_hh + (size_t)col0 * HH + kbase + 2 * HELD_PAIRS);
        const float4* t1 = reinterpret_cast<const float4*>(W_hh + (size_t)col1 * HH + kbase + 2 * HELD_PAIRS);
        #pragma unroll
        for (int i = 0; i < STR_QUADS; i++) {
            WS[i * 512 + tid] = t0[i];
            WS[(STR_QUADS + i) * 512 + tid] = t1[i];
        }
    }
    if (tid < 2 * HH) h_s[tid] = 0.f;

    // ---- finalizer state: thread (j2<128, q) owns (row=q, hc=j2) ----
    const bool exec = (j2 < 128);
    const int hc = j2;
    const int len = lengths[b0 + q];
    float c_reg = 0.f, h_reg = 0.f;
    const float* gxp = g_gx + ((size_t)(b0 + q) * TT) * GG;
    float gxi = 0.f, gxf = 0.f, gxg = 0.f, gxo = 0.f;
    if (exec) {
        gxi = __ldg(gxp + hc);
        gxf = __ldg(gxp + HH + hc);
        gxg = __ldg(gxp + 2 * HH + hc);
        gxo = __ldg(gxp + 3 * HH + hc);
    }

    const ulonglong2* h2 = reinterpret_cast<const ulonglong2*>(h_s);  // [2][32]
    const ulonglong2* WSu = reinterpret_cast<const ulonglong2*>(WS);
    const int hoff = q * 16;

    for (int t = 0; t < TT; t++) {
        __syncthreads();   // S0: h_s(t-1) final, P(t-1) consumed

        // ---- phase A: partial dots over this thread's k-half ----
        u64 a00 = 0ull, a01 = 0ull, a10 = 0ull, a11 = 0ull;  // a[row][colpair]
        #pragma unroll
        for (int i = 0; i < HELD_PAIRS / 2; i++) {           // k_local 0..39
            ulonglong2 h0 = h2[hoff + i];
            ulonglong2 h1 = h2[32 + hoff + i];
            u64 wc0a = wa[2*i], wc0b = wa[2*i+1];
            u64 wc1a = wa[HELD_PAIRS + 2*i], wc1b = wa[HELD_PAIRS + 2*i+1];  // FIX
            a00 = ffma2(wc0a, h0.x, a00); a00 = ffma2(wc0b, h0.y, a00);
            a01 = ffma2(wc1a, h0.x, a01); a01 = ffma2(wc1b, h0.y, a01);
            a10 = ffma2(wc0a, h1.x, a10); a10 = ffma2(wc0b, h1.y, a10);
            a11 = ffma2(wc1a, h1.x, a11); a11 = ffma2(wc1b, h1.y, a11);
        }
        #pragma unroll
        for (int i = 0; i < STR_QUADS; i++) {                // k_local 40..63 streamed
            ulonglong2 s0 = WSu[i * 512 + tid];
            ulonglong2 s1 = WSu[(STR_QUADS + i) * 512 + tid];
            ulonglong2 h0 = h2[hoff + HELD_PAIRS / 2 + i];
            ulonglong2 h1 = h2[32 + hoff + HELD_PAIRS / 2 + i];
            a00 = ffma2(s0.x, h0.x, a00); a00 = ffma2(s0.y, h0.y, a00);
            a01 = ffma2(s1.x, h0.x, a01); a01 = ffma2(s1.y, h0.y, a01);
            a10 = ffma2(s0.x, h1.x, a10); a10 = ffma2(s0.y, h1.y, a10);
            a11 = ffma2(s1.x, h1.x, a11); a11 = ffma2(s1.y, h1.y, a11);
        }
        float2 f00 = unpackf2(a00), f01 = unpackf2(a01);
        float2 f10 = unpackf2(a10), f11 = unpackf2(a11);
        float p00 = f00.x + f00.y;   // (row0, col0)
        float p01 = f01.x + f01.y;   // (row0, col1)
        float p10 = f10.x + f10.y;   // (row1, col0)
        float p11 = f11.x + f11.y;   // (row1, col1)
        P[tid] = make_float4(p00, p01, p10, p11);

        __syncthreads();   // S1: partials ready

        // ---- phase B+C: finalize + pointwise (warp-uniform branch) ----
        if (exec) {
            const float* Pf = reinterpret_cast<const float*>(P);
            // own columns {hc, hc+256} = gates (i,g), other k-half partials
            float2 pown = *reinterpret_cast<const float2*>(Pf + (((1 - q) << 8) + hc) * 4 + q * 2);
            // columns {hc+128, hc+384} = gates (f,o), both k-halves
            float2 pa = *reinterpret_cast<const float2*>(Pf + (128 + hc) * 4 + q * 2);
            float2 pb = *reinterpret_cast<const float2*>(Pf + (256 + 128 + hc) * 4 + q * 2);
            float ownc0 = q ? p10 : p00;
            float ownc1 = q ? p11 : p01;
            float gi  = ownc0 + pown.x + gxi;
            float ggv = ownc1 + pown.y + gxg;
            float gf  = pa.x + pb.x + gxf;
            float go  = pa.y + pb.y + gxo;
            float i_ = sigmoidf_fast(gi);
            float f_ = sigmoidf_fast(gf);
            float g_ = tanhf_fast(ggv);
            float o_ = sigmoidf_fast(go);
            float cn = fmaf(f_, c_reg, i_ * g_);
            float hn = o_ * tanhf_fast(cn);
            bool m = (t < len);
            h_reg = m ? hn : h_reg;
            c_reg = m ? cn : c_reg;
            h_s[q * HH + hc] = h_reg;
            outs[((size_t)(b0 + q) * TT + t) * HH + hc] = m ? hn : 0.f;
            // prefetch gx(t+1) — hidden behind next phase A
            if (t + 1 < TT) {
                const float* gn = gxp + (size_t)(t + 1) * GG;
                gxi = __ldg(gn + hc);
                gxf = __ldg(gn + HH + hc);
                gxg = __ldg(gn + 2 * HH + hc);
                gxo = __ldg(gn + 3 * HH + hc);
            }
        }
    }

    if (exec) {
        h_out[(size_t)(b0 + q) * HH + hc] = h_reg;
        c_out[(size_t)(b0 + q) * HH + hc] = c_reg;
    }
}

// ---------------------------------------------------------------------------
// kernel_launch — graph-capturable: 4 launches on the default stream.
// Output: outputs[B,T,H] | h[1,B,H] | c[1,B,H] | embedded[B,T,E]
// ---------------------------------------------------------------------------
extern "C" void kernel_launch(void* const* d_in, const int* in_sizes, int n_in,
                              void* d_out, int out_size) {
    const int*   obs_ids     = (const int*)d_in[0];
    const int*   obs_slot    = (const int*)d_in[1];
    const int*   action_ids  = (const int*)d_in[2];
    const int*   is_action   = (const int*)d_in[3];
    const int*   lengths     = (const int*)d_in[4];
    const float* action_emb  = (const float*)d_in[5];
    const float* obs_emb     = (const float*)d_in[6];
    const float* W_ih        = (const float*)d_in[7];
    const float* W_hh        = (const float*)d_in[8];
    const float* b_ih        = (const float*)d_in[9];
    const float* b_hh        = (const float*)d_in[10];

    float* out   = (float*)d_out;
    float* outs  = out;                                    // B*T*H
    float* h_out = out + (size_t)BB * TT * HH;             // B*H
    float* c_out = h_out + (size_t)BB * HH;                // B*H
    float* emb   = c_out + (size_t)BB * HH;                // B*T*E

    cudaFuncSetAttribute(lstm_kernel,
                         cudaFuncAttributeMaxDynamicSharedMemorySize, SMEM_TOTAL);

    // 1) embedded = is_action ? action_emb[aid] : 0
    {
        int nthreads = BB * TT * 8;
        embed_init_kernel<<<nthreads / 256, 256>>>(action_ids, is_action,
                                                   action_emb, emb);
    }
    // 2) scatter-add observation embeddings into non-action slots
    {
        int n_obs = in_sizes[0];
        int nthreads = n_obs * 8;
        int blocks = (nthreads + 255) / 256;
        obs_scatter_kernel<<<blocks, 256>>>(obs_ids, obs_slot, is_action,
                                            obs_emb, emb, nthreads);
    }
    // 3) x-projection pre-GEMM: gx = bias + emb @ Wih^T  (262144 x 512)
    gatex_kernel<<<SLOTS / XCHUNK, 256>>>(emb, W_ih, b_ih, b_hh);

    // 4) persistent LSTM recurrence: 128 CTAs x 512 threads, 1 CTA/SM
    lstm_kernel<<<BB / 2, 512, SMEM_TOTAL>>>(W_hh, lengths, outs, h_out, c_out);
}